// round 11
// baseline (speedup 1.0000x reference)
#include <cuda_runtime.h>
#include <cuda_bf16.h>
#include <cstdint>
#include <cstddef>

// ---------------------------------------------------------------------------
// Problem constants
// ---------------------------------------------------------------------------
#define BATCH   64
#define SEQ     512
#define DM      256
#define HID     512
#define G3      1536          // 3*HID
#define NCLS    2

// Recurrent kernel partitioning
#define NGRP    8             // batch groups
#define NB      8             // batches per group (NGRP*NB = 64)
#define NCG     16            // CTAs per group (hidden slices)
#define NU      32            // hidden units per CTA (NCG*NU = 512)
#define KPAD    516           // mu*516*4 % 128 = mu*16 -> conflict-free W phases
#define NCTA_B  (NGRP*NCG)    // 128 CTAs, all co-resident on 148 SMs
#define RSTR    25            // red_s unit stride (conflict-free gate reads)
#define NKH     4             // kh quarters (one per warp-quad)

typedef unsigned long long ull;

// ---------------------------------------------------------------------------
// Device scratch (allocation-free: __device__ globals)
// ---------------------------------------------------------------------------
__device__ float    g_xg[(size_t)BATCH * SEQ * G3];   // precomputed input gates
__device__ float    g_h[2][NGRP][NB][HID];            // ping-pong hidden state
__device__ unsigned g_flag2[NGRP * NCG * 32];         // per-(grp,slice) flags, 128B apart

// ---------------------------------------------------------------------------
// Packed f32x2 helpers (Blackwell FFMA2: 2 MACs / instruction)
// ---------------------------------------------------------------------------
__device__ __forceinline__ ull ff2(ull a, ull b, ull c) {
    ull d;
    asm("fma.rn.f32x2 %0, %1, %2, %3;" : "=l"(d) : "l"(a), "l"(b), "l"(c));
    return d;
}
__device__ __forceinline__ float f2lo(ull v) { return __uint_as_float((unsigned)v); }
__device__ __forceinline__ float f2hi(ull v) { return __uint_as_float((unsigned)(v >> 32)); }
__device__ __forceinline__ float f2sum(ull v) { return f2lo(v) + f2hi(v); }

__device__ __forceinline__ float sig_fast(float x) {
    return __fdividef(1.0f, 1.0f + __expf(-x));
}
__device__ __forceinline__ float tanh_fast(float x) {
    return 1.0f - __fdividef(2.0f, __expf(2.0f * x) + 1.0f);
}

// tf32 round-to-nearest (rna) — applied once at SMEM fill time
__device__ __forceinline__ float tf32r(float x) {
    unsigned u;
    asm("cvt.rna.tf32.f32 %0, %1;" : "=r"(u) : "f"(x));
    return __uint_as_float(u);
}

// ---------------------------------------------------------------------------
// Kernel A: xg[m, :] = emb[ids[m]] @ Wx + bx     (M=32768, N=1536, K=256)
// tf32 mma.sync.m16n8k8: warp (wm,wn) owns 16M x 64N; operands pre-rounded
// to tf32 (rna) at SMEM fill; fp32 accumulate; fp32 bias epilogue.
// ---------------------------------------------------------------------------
#define APAD 68
#define BPAD 132

__global__ __launch_bounds__(256) void xg_kernel(
    const int*   __restrict__ ids,
    const float* __restrict__ emb,
    const float* __restrict__ Wx,
    const float* __restrict__ bx)
{
    __shared__ float As[32 * APAD];   // [k][m], tf32-rounded values
    __shared__ float Bs[32 * BPAD];   // [k][n], tf32-rounded values
    __shared__ int   rid[64];

    const int tid   = threadIdx.x;
    const int nbase = blockIdx.x * 128;
    const int mbase = blockIdx.y * 64;

    const int wid  = tid >> 5;
    const int lane = tid & 31;
    const int wm   = wid & 3;          // m-block: rows wm*16..+15
    const int wn   = wid >> 2;         // n-block: cols wn*64..+63
    const int gid  = lane >> 2;        // groupID 0..7
    const int tig  = lane & 3;         // thread-in-group 0..3

    if (tid < 64) rid[tid] = ids[mbase + tid];
    __syncthreads();

    // loader indices (same as proven loader)
    const int lm  = tid >> 2;          // 0..63  (A row)
    const int lkq = (tid & 3) * 4;     // 0,4,8,12 (A k quad)
    const int ln  = (tid & 31) * 4;    // 0..124 (B n quad)
    const int lk  = tid >> 5;          // 0..7   (B k row base)

    float acc[8][4];
#pragma unroll
    for (int nt = 0; nt < 8; nt++)
#pragma unroll
        for (int c = 0; c < 4; c++) acc[nt][c] = 0.0f;

    for (int kb = 0; kb < DM; kb += 32) {
        const float* erow = emb + (size_t)rid[lm] * DM + kb + lkq;
        float4 a0 = *(const float4*)erow;
        float4 a1 = *(const float4*)(erow + 16);
        float4 bld[4];
#pragma unroll
        for (int j = 0; j < 4; j++) {
            int k = lk + 8 * j;
            bld[j] = *(const float4*)(Wx + (size_t)(kb + k) * G3 + nbase + ln);
        }
        __syncthreads();
        // store A transposed [k][m], tf32-rounded
        As[(lkq + 0)  * APAD + lm] = tf32r(a0.x);
        As[(lkq + 1)  * APAD + lm] = tf32r(a0.y);
        As[(lkq + 2)  * APAD + lm] = tf32r(a0.z);
        As[(lkq + 3)  * APAD + lm] = tf32r(a0.w);
        As[(lkq + 16) * APAD + lm] = tf32r(a1.x);
        As[(lkq + 17) * APAD + lm] = tf32r(a1.y);
        As[(lkq + 18) * APAD + lm] = tf32r(a1.z);
        As[(lkq + 19) * APAD + lm] = tf32r(a1.w);
        // store B [k][n], tf32-rounded
#pragma unroll
        for (int j = 0; j < 4; j++) {
            int k = lk + 8 * j;
            float4 v;
            v.x = tf32r(bld[j].x);
            v.y = tf32r(bld[j].y);
            v.z = tf32r(bld[j].z);
            v.w = tf32r(bld[j].w);
            *(float4*)&Bs[k * BPAD + ln] = v;
        }
        __syncthreads();

#pragma unroll
        for (int k8 = 0; k8 < 4; k8++) {
            const int kk = 8 * k8;
            // A fragment (m16 x k8), row-major: a0/a1 cols tig, a2/a3 cols tig+4
            unsigned ua0 = __float_as_uint(As[(kk + tig)     * APAD + wm * 16 + gid]);
            unsigned ua1 = __float_as_uint(As[(kk + tig)     * APAD + wm * 16 + gid + 8]);
            unsigned ua2 = __float_as_uint(As[(kk + tig + 4) * APAD + wm * 16 + gid]);
            unsigned ua3 = __float_as_uint(As[(kk + tig + 4) * APAD + wm * 16 + gid + 8]);
#pragma unroll
            for (int nt = 0; nt < 8; nt++) {
                const int n0 = wn * 64 + nt * 8;
                unsigned ub0 = __float_as_uint(Bs[(kk + tig)     * BPAD + n0 + gid]);
                unsigned ub1 = __float_as_uint(Bs[(kk + tig + 4) * BPAD + n0 + gid]);
                asm volatile(
                    "mma.sync.aligned.m16n8k8.row.col.f32.tf32.tf32.f32 "
                    "{%0,%1,%2,%3}, {%4,%5,%6,%7}, {%8,%9}, {%0,%1,%2,%3};\n"
                    : "+f"(acc[nt][0]), "+f"(acc[nt][1]),
                      "+f"(acc[nt][2]), "+f"(acc[nt][3])
                    : "r"(ua0), "r"(ua1), "r"(ua2), "r"(ua3),
                      "r"(ub0), "r"(ub1));
            }
        }
    }

    // epilogue: += bx, store.  c0/c1: (row=gid, cols 2tig..+1); c2/c3: row gid+8
#pragma unroll
    for (int nt = 0; nt < 8; nt++) {
        const int ncol = nbase + wn * 64 + nt * 8 + 2 * tig;
        float2 bxv = *(const float2*)&bx[ncol];
        const int m0 = mbase + wm * 16 + gid;
        float2 v01, v23;
        v01.x = acc[nt][0] + bxv.x;
        v01.y = acc[nt][1] + bxv.y;
        v23.x = acc[nt][2] + bxv.x;
        v23.y = acc[nt][3] + bxv.y;
        *(float2*)&g_xg[(size_t)m0 * G3 + ncol]       = v01;
        *(float2*)&g_xg[(size_t)(m0 + 8) * G3 + ncol] = v23;
    }
}

// ---------------------------------------------------------------------------
// Kernel B: persistent GRU scan (R9/R5 verbatim — best measured).
// 512 threads (16 warps = 4/SMSP); K split 16 ways; per-slice flag barrier.
// ---------------------------------------------------------------------------
#define SMEM_WH   (3 * NU * KPAD)            // 49536 floats
#define SMEM_H    (NB * HID)                 // 4096 floats
#define SMEM_RED  (NKH * NU * RSTR)          // 3200 floats (four kh quarters)
#define SMEM_SCAN ((SMEM_WH + SMEM_H + SMEM_RED) * 4)   // 227,328 bytes

__global__ __launch_bounds__(512, 1) void scan_kernel(
    const float* __restrict__ Wh,
    const float* __restrict__ bh)
{
    extern __shared__ float sm[];
    float* Whs   = sm;                     // [3][NU][KPAD]
    float* h_s   = sm + SMEM_WH;           // [NB][HID]
    float* red_s = h_s + SMEM_H;           // [NKH][NU][RSTR]

    const int tid = threadIdx.x;
    const int cta = blockIdx.x;
    const int grp = cta >> 4;              // 0..7
    const int sl  = cta & 15;              // 0..15

    // ---- load Wh slice into SMEM (one-time) ----
    for (int idx = tid; idx < 3 * HID * NU; idx += 512) {
        int u = idx & 31;
        int rest = idx >> 5;               // g*512 + k
        int k = rest & 511;
        int g = rest >> 9;
        Whs[(g * NU + u) * KPAD + k] = Wh[(size_t)k * G3 + g * HID + sl * NU + u];
    }
    for (int i = tid; i < NB * HID; i += 512) h_s[i] = 0.0f;

    // ---- gate-math thread constants: threads 0..255 as (gb, gu) ----
    const int gb = (tid >> 5) & 7;         // batch within group (for tid<256)
    const int gu = tid & 31;               // unit within slice
    const int b_glob = grp * NB + gb;
    const float* xgp = g_xg + (size_t)b_glob * SEQ * G3 + sl * NU + gu;
    const float bhr = bh[0 * HID + sl * NU + gu];
    const float bhz = bh[1 * HID + sl * NU + gu];
    const float bhn = bh[2 * HID + sl * NU + gu];

    // ---- matvec thread constants: broadcast-friendly mapping ----
    const int wid  = tid >> 5;                      // 0..15
    const int lane = tid & 31;
    const int mu = (lane & 7) + ((wid & 3) << 3);   // 0..31
    const int kl = lane >> 3;                       // 0..3
    const int kh = wid >> 2;                        // 0..3
    const int ks = kl + 4 * kh;                     // 0..15
    const float* wr = Whs + (0 * NU + mu) * KPAD + 4 * ks;
    const float* wz = Whs + (1 * NU + mu) * KPAD + 4 * ks;
    const float* wn = Whs + (2 * NU + mu) * KPAD + 4 * ks;
    const int s1 = kl & 1, s2 = kl >> 1;
    float* redw = red_s + kh * (NU * RSTR) + mu * RSTR;

    // ---- barrier constants: warp w owns slice w ----
    unsigned* my_flag = g_flag2 + (grp * NCG + sl) * 32;
    const int cb = lane >> 2;              // copy row 0..7
    const int cq = lane & 3;               // copy quad 0..3

    __syncthreads();

    for (int t = 0; t < SEQ; ++t) {
        // prefetch this step's xg (independent of the barrier); tid<256 only
        float xr = 0.f, xz = 0.f, xn = 0.f;
        if (tid < 256) {
            xr = __ldcs(xgp + 0 * HID);
            xz = __ldcs(xgp + 1 * HID);
            xn = __ldcs(xgp + 2 * HID);
        }
        xgp += G3;

        if (t > 0) {
            // warp wid waits on slice wid's flag, then copies that 1KB slice
            const int s = wid;
            const unsigned* fp = g_flag2 + (grp * NCG + s) * 32;
            if (lane == 0) {
                unsigned v;
                do {
                    asm volatile("ld.acquire.gpu.u32 %0, [%1];"
                                 : "=r"(v) : "l"(fp) : "memory");
                } while (v < (unsigned)t);
            }
            __syncwarp();
            const float4* src = (const float4*)&g_h[t & 1][grp][cb][s * NU];
            float4 v0 = __ldcg(src + cq);
            float4 v1 = __ldcg(src + cq + 4);
            float4* dst = (float4*)&h_s[cb * HID + s * NU];
            dst[cq]     = v0;
            dst[cq + 4] = v1;
            __syncthreads();
        }

        // ---- matvec: partials over k in {4ks..4ks+3} + 64i ----
        ull ar[NB], az[NB], an_[NB];
#pragma unroll
        for (int b = 0; b < NB; b++) { ar[b] = 0ULL; az[b] = 0ULL; an_[b] = 0ULL; }

#pragma unroll
        for (int i = 0; i < 8; i++) {
            int k = 64 * i;
            ulonglong2 wrv = *(const ulonglong2*)(wr + k);
            ulonglong2 wzv = *(const ulonglong2*)(wz + k);
            ulonglong2 wnv = *(const ulonglong2*)(wn + k);
#pragma unroll
            for (int b = 0; b < NB; b++) {
                ulonglong2 hv = *(const ulonglong2*)(h_s + b * HID + 4 * ks + k);
                ar[b]  = ff2(wrv.x, hv.x, ar[b]);
                az[b]  = ff2(wzv.x, hv.x, az[b]);
                an_[b] = ff2(wnv.x, hv.x, an_[b]);
                ar[b]  = ff2(wrv.y, hv.y, ar[b]);
                az[b]  = ff2(wzv.y, hv.y, az[b]);
                an_[b] = ff2(wnv.y, hv.y, an_[b]);
            }
        }

        // ---- intra-warp butterfly reduce over kl (xor 8, xor 16) ----
        {
            float vr[NB], vz[NB], vn[NB];
#pragma unroll
            for (int b = 0; b < NB; b++) {
                vr[b] = f2sum(ar[b]); vz[b] = f2sum(az[b]); vn[b] = f2sum(an_[b]);
            }
            float ar_[4], az2[4], an2[4];
#pragma unroll
            for (int j = 0; j < 4; j++) {
                float gr = s1 ? vr[2*j] : vr[2*j+1];
                float gz = s1 ? vz[2*j] : vz[2*j+1];
                float gn = s1 ? vn[2*j] : vn[2*j+1];
                ar_[j] = (s1 ? vr[2*j+1] : vr[2*j]) + __shfl_xor_sync(0xffffffffu, gr, 8);
                az2[j] = (s1 ? vz[2*j+1] : vz[2*j]) + __shfl_xor_sync(0xffffffffu, gz, 8);
                an2[j] = (s1 ? vn[2*j+1] : vn[2*j]) + __shfl_xor_sync(0xffffffffu, gn, 8);
            }
            float fr[2], fz[2], fn[2];
#pragma unroll
            for (int m = 0; m < 2; m++) {
                float gr = s2 ? ar_[2*m] : ar_[2*m+1];
                float gz = s2 ? az2[2*m] : az2[2*m+1];
                float gn = s2 ? an2[2*m] : an2[2*m+1];
                fr[m] = (s2 ? ar_[2*m+1] : ar_[2*m]) + __shfl_xor_sync(0xffffffffu, gr, 16);
                fz[m] = (s2 ? az2[2*m+1] : az2[2*m]) + __shfl_xor_sync(0xffffffffu, gz, 16);
                fn[m] = (s2 ? an2[2*m+1] : an2[2*m]) + __shfl_xor_sync(0xffffffffu, gn, 16);
            }
#pragma unroll
            for (int m = 0; m < 2; m++) {
                int b = 4 * m + kl;
                redw[0  + b] = fr[m];
                redw[8  + b] = fz[m];
                redw[16 + b] = fn[m];
            }
        }
        __syncthreads();

        // ---- gate math: threads 0..255 as (gb, gu); sum 4 kh quarters ----
        if (tid < 256) {
            const float* r0p = red_s + gu * RSTR;
            const float* r1p = r0p + 1 * (NU * RSTR);
            const float* r2p = r0p + 2 * (NU * RSTR);
            const float* r3p = r0p + 3 * (NU * RSTR);
            float hr = (r0p[0  + gb] + r1p[0  + gb]) + (r2p[0  + gb] + r3p[0  + gb]) + bhr;
            float hz = (r0p[8  + gb] + r1p[8  + gb]) + (r2p[8  + gb] + r3p[8  + gb]) + bhz;
            float hn = (r0p[16 + gb] + r1p[16 + gb]) + (r2p[16 + gb] + r3p[16 + gb]) + bhn;
            float hold = h_s[gb * HID + sl * NU + gu];
            float r = sig_fast(xr + hr);
            float z = sig_fast(xz + hz);
            float n = tanh_fast(xn + r * hn);
            float hnew = (1.0f - z) * n + z * hold;
            g_h[(t + 1) & 1][grp][gb][sl * NU + gu] = hnew;
        }
        __syncthreads();

        // ---- publish: release-store own flag (cumulativity via syncthreads) ----
        if (tid == 0) {
            unsigned fv = (unsigned)(t + 1);
            asm volatile("st.release.gpu.u32 [%0], %1;"
                         :: "l"(my_flag), "r"(fv) : "memory");
        }
    }
}

// ---------------------------------------------------------------------------
// Kernel C: logits = h_last @ Wo + bo   (h_512 lives in g_h[0])
// ---------------------------------------------------------------------------
__global__ void head_kernel(const float* __restrict__ Wo,
                            const float* __restrict__ bo,
                            float* __restrict__ out)
{
    int tid = threadIdx.x;      // 128 threads
    int b = tid >> 1, c = tid & 1;
    const float* h = &g_h[0][b >> 3][b & 7][0];
    float s = bo[c];
#pragma unroll 8
    for (int u = 0; u < HID; u++)
        s += h[u] * Wo[u * NCLS + c];
    out[b * NCLS + c] = s;
}

// ---------------------------------------------------------------------------
// Kernel D: reset barrier state. Runs FIRST in each call (semantics-preserving:
// flags are zero-initialized and re-zeroed before each scan).
// ---------------------------------------------------------------------------
__global__ void reset_kernel() {
    int i = threadIdx.x;
    for (int j = i; j < NGRP * NCG * 32; j += 256) g_flag2[j] = 0u;
}

// Dummy: shifts launch-position so ncu's -s 5 window lands on scan_kernel.
__global__ void dummy_kernel() {}

// ---------------------------------------------------------------------------
// kernel_launch — order [reset, dummy, xg, scan, head]: with the 2 hidden
// harness launches, ncu (-s 5 -c 1) captures launch 6 = scan_kernel.
// ---------------------------------------------------------------------------
extern "C" void kernel_launch(void* const* d_in, const int* in_sizes, int n_in,
                              void* d_out, int out_size)
{
    const int*   ids = (const int*)d_in[0];
    const float* emb = (const float*)d_in[1];
    const float* Wx  = (const float*)d_in[2];
    const float* Wh  = (const float*)d_in[3];
    const float* bx  = (const float*)d_in[4];
    const float* bh  = (const float*)d_in[5];
    const float* Wo  = (const float*)d_in[6];
    const float* bo  = (const float*)d_in[7];
    float* out = (float*)d_out;

    cudaFuncSetAttribute(scan_kernel,
                         cudaFuncAttributeMaxDynamicSharedMemorySize, SMEM_SCAN);

    reset_kernel<<<1, 256>>>();
    dummy_kernel<<<1, 32>>>();
    dim3 gx(G3 / 128, (BATCH * SEQ) / 64);   // (12, 512)
    xg_kernel<<<gx, 256>>>(ids, emb, Wx, bx);
    scan_kernel<<<NCTA_B, 512, SMEM_SCAN>>>(Wh, bh);
    head_kernel<<<1, 128>>>(Wo, bo, out);
}

// round 12
// speedup vs baseline: 1.4264x; 1.4264x over previous
#include <cuda_runtime.h>
#include <cuda_bf16.h>
#include <cstdint>
#include <cstddef>

// ---------------------------------------------------------------------------
// Problem constants
// ---------------------------------------------------------------------------
#define BATCH   64
#define SEQ     512
#define DM      256
#define HID     512
#define G3      1536          // 3*HID
#define NCLS    2

// Recurrent kernel partitioning
#define NGRP    8             // batch groups
#define NB      8             // batches per group (NGRP*NB = 64)
#define NCG     16            // CTAs per group (hidden slices)
#define NU      32            // hidden units per CTA (NCG*NU = 512)
#define KPAD    516           // mu*516*4 % 128 = mu*16 -> conflict-free W phases
#define NCTA_B  (NGRP*NCG)    // 128 CTAs, all co-resident on 148 SMs
#define RSTR    25            // red_s unit stride (conflict-free gate reads)
#define NKH     4             // kh quarters (one per warp-quad)

typedef unsigned long long ull;

// ---------------------------------------------------------------------------
// Device scratch (allocation-free: __device__ globals)
// ---------------------------------------------------------------------------
__device__ float    g_xg[(size_t)BATCH * SEQ * G3];   // precomputed input gates
__device__ float    g_h[2][NGRP][NB][HID];            // ping-pong hidden state
__device__ unsigned g_flag2[NGRP * NCG * 32];         // per-(grp,slice) flags, 128B apart

// ---------------------------------------------------------------------------
// Packed f32x2 helpers (Blackwell FFMA2: 2 MACs / instruction)
// ---------------------------------------------------------------------------
__device__ __forceinline__ ull ff2(ull a, ull b, ull c) {
    ull d;
    asm("fma.rn.f32x2 %0, %1, %2, %3;" : "=l"(d) : "l"(a), "l"(b), "l"(c));
    return d;
}
__device__ __forceinline__ ull dup2(float x) {
    ull d; unsigned r = __float_as_uint(x);
    asm("mov.b64 %0, {%1, %1};" : "=l"(d) : "r"(r));
    return d;
}
__device__ __forceinline__ float f2lo(ull v) { return __uint_as_float((unsigned)v); }
__device__ __forceinline__ float f2hi(ull v) { return __uint_as_float((unsigned)(v >> 32)); }
__device__ __forceinline__ float f2sum(ull v) { return f2lo(v) + f2hi(v); }

__device__ __forceinline__ float sig_fast(float x) {
    return __fdividef(1.0f, 1.0f + __expf(-x));
}
__device__ __forceinline__ float tanh_fast(float x) {
    return 1.0f - __fdividef(2.0f, __expf(2.0f * x) + 1.0f);
}

// ---------------------------------------------------------------------------
// Kernel A: xg[m, :] = emb[ids[m]] @ Wx + bx     (M=32768, N=1536, K=256)
// Conflict-free N-microtile: thread tx owns col pairs {2tx,2tx+1}+32m.
// Per-LDS.64 bank pattern = 2tx -> all 32 banks, 1 phase.
// ---------------------------------------------------------------------------
#define APAD 68
#define BPAD 132

__global__ __launch_bounds__(256) void xg_kernel(
    const int*   __restrict__ ids,
    const float* __restrict__ emb,
    const float* __restrict__ Wx,
    const float* __restrict__ bx)
{
    __shared__ float As[32 * APAD];   // [k][m], m contiguous
    __shared__ float Bs[32 * BPAD];   // [k][n], n contiguous
    __shared__ int   rid[64];

    const int tid   = threadIdx.x;
    const int nbase = blockIdx.x * 128;
    const int mbase = blockIdx.y * 64;
    const int tx    = tid & 15;       // col pairs {2tx,2tx+1} + 32m
    const int ty    = tid >> 4;       // rows ty*4 .. +3

    if (tid < 64) rid[tid] = ids[mbase + tid];
    __syncthreads();

    const int lm  = tid >> 2;
    const int lkq = (tid & 3) * 4;
    const int ln  = (tid & 31) * 4;
    const int lk  = tid >> 5;

    ull acc[4][4];
#pragma unroll
    for (int i = 0; i < 4; i++)
#pragma unroll
        for (int j = 0; j < 4; j++) acc[i][j] = 0ULL;

    for (int kb = 0; kb < DM; kb += 32) {
        const float* erow = emb + (size_t)rid[lm] * DM + kb + lkq;
        float4 a0 = *(const float4*)erow;
        float4 a1 = *(const float4*)(erow + 16);
        float4 bld[4];
#pragma unroll
        for (int j = 0; j < 4; j++) {
            int k = lk + 8 * j;
            bld[j] = *(const float4*)(Wx + (size_t)(kb + k) * G3 + nbase + ln);
        }
        __syncthreads();
        As[(lkq + 0) * APAD + lm] = a0.x;
        As[(lkq + 1) * APAD + lm] = a0.y;
        As[(lkq + 2) * APAD + lm] = a0.z;
        As[(lkq + 3) * APAD + lm] = a0.w;
        As[(lkq + 16) * APAD + lm] = a1.x;
        As[(lkq + 17) * APAD + lm] = a1.y;
        As[(lkq + 18) * APAD + lm] = a1.z;
        As[(lkq + 19) * APAD + lm] = a1.w;
#pragma unroll
        for (int j = 0; j < 4; j++) {
            int k = lk + 8 * j;
            *(float4*)&Bs[k * BPAD + ln] = bld[j];
        }
        __syncthreads();

#pragma unroll 8
        for (int k = 0; k < 32; k++) {
            float4 av = *(const float4*)&As[k * APAD + ty * 4];
            const float* bp = &Bs[k * BPAD + 2 * tx];
            ull b0 = *(const ull*)(bp + 0);
            ull b1 = *(const ull*)(bp + 32);
            ull b2 = *(const ull*)(bp + 64);
            ull b3 = *(const ull*)(bp + 96);
            ull ad;
            ad = dup2(av.x);
            acc[0][0] = ff2(ad, b0, acc[0][0]); acc[0][1] = ff2(ad, b1, acc[0][1]);
            acc[0][2] = ff2(ad, b2, acc[0][2]); acc[0][3] = ff2(ad, b3, acc[0][3]);
            ad = dup2(av.y);
            acc[1][0] = ff2(ad, b0, acc[1][0]); acc[1][1] = ff2(ad, b1, acc[1][1]);
            acc[1][2] = ff2(ad, b2, acc[1][2]); acc[1][3] = ff2(ad, b3, acc[1][3]);
            ad = dup2(av.z);
            acc[2][0] = ff2(ad, b0, acc[2][0]); acc[2][1] = ff2(ad, b1, acc[2][1]);
            acc[2][2] = ff2(ad, b2, acc[2][2]); acc[2][3] = ff2(ad, b3, acc[2][3]);
            ad = dup2(av.w);
            acc[3][0] = ff2(ad, b0, acc[3][0]); acc[3][1] = ff2(ad, b1, acc[3][1]);
            acc[3][2] = ff2(ad, b2, acc[3][2]); acc[3][3] = ff2(ad, b3, acc[3][3]);
        }
    }

    // epilogue: += bx, STG.64 per (row, pair) — coalesced 128B per instruction
    float2 bxv[4];
#pragma unroll
    for (int m = 0; m < 4; m++)
        bxv[m] = *(const float2*)&bx[nbase + 2 * tx + 32 * m];
#pragma unroll
    for (int i = 0; i < 4; i++) {
        int mrow = mbase + ty * 4 + i;
        float* o = g_xg + (size_t)mrow * G3 + nbase + 2 * tx;
#pragma unroll
        for (int m = 0; m < 4; m++) {
            float2 v;
            v.x = f2lo(acc[i][m]) + bxv[m].x;
            v.y = f2hi(acc[i][m]) + bxv[m].y;
            *(float2*)(o + 32 * m) = v;
        }
    }
}

// ---------------------------------------------------------------------------
// Kernel B: persistent GRU scan (R5 structure — best measured).
// 512 threads (16 warps = 4/SMSP); K split 16 ways; per-slice flag barrier.
// ---------------------------------------------------------------------------
#define SMEM_WH   (3 * NU * KPAD)            // 49536 floats
#define SMEM_H    (NB * HID)                 // 4096 floats
#define SMEM_RED  (NKH * NU * RSTR)          // 3200 floats (four kh quarters)
#define SMEM_SCAN ((SMEM_WH + SMEM_H + SMEM_RED) * 4)   // 227,328 bytes

__global__ __launch_bounds__(512, 1) void scan_kernel(
    const float* __restrict__ Wh,
    const float* __restrict__ bh)
{
    extern __shared__ float sm[];
    float* Whs   = sm;                     // [3][NU][KPAD]
    float* h_s   = sm + SMEM_WH;           // [NB][HID]
    float* red_s = h_s + SMEM_H;           // [NKH][NU][RSTR]

    const int tid = threadIdx.x;
    const int cta = blockIdx.x;
    const int grp = cta >> 4;              // 0..7
    const int sl  = cta & 15;              // 0..15

    // ---- load Wh slice into SMEM (one-time) ----
    for (int idx = tid; idx < 3 * HID * NU; idx += 512) {
        int u = idx & 31;
        int rest = idx >> 5;               // g*512 + k
        int k = rest & 511;
        int g = rest >> 9;
        Whs[(g * NU + u) * KPAD + k] = Wh[(size_t)k * G3 + g * HID + sl * NU + u];
    }
    for (int i = tid; i < NB * HID; i += 512) h_s[i] = 0.0f;

    // ---- gate-math thread constants: threads 0..255 as (gb, gu) ----
    const int gb = (tid >> 5) & 7;         // batch within group (for tid<256)
    const int gu = tid & 31;               // unit within slice
    const int b_glob = grp * NB + gb;
    const float* xgp = g_xg + (size_t)b_glob * SEQ * G3 + sl * NU + gu;
    const float bhr = bh[0 * HID + sl * NU + gu];
    const float bhz = bh[1 * HID + sl * NU + gu];
    const float bhn = bh[2 * HID + sl * NU + gu];

    // ---- matvec thread constants: broadcast-friendly mapping ----
    const int wid  = tid >> 5;                      // 0..15
    const int lane = tid & 31;
    const int mu = (lane & 7) + ((wid & 3) << 3);   // 0..31
    const int kl = lane >> 3;                       // 0..3
    const int kh = wid >> 2;                        // 0..3
    const int ks = kl + 4 * kh;                     // 0..15
    const float* wr = Whs + (0 * NU + mu) * KPAD + 4 * ks;
    const float* wz = Whs + (1 * NU + mu) * KPAD + 4 * ks;
    const float* wn = Whs + (2 * NU + mu) * KPAD + 4 * ks;
    const int s1 = kl & 1, s2 = kl >> 1;
    float* redw = red_s + kh * (NU * RSTR) + mu * RSTR;

    // ---- barrier constants: warp w owns slice w ----
    unsigned* my_flag = g_flag2 + (grp * NCG + sl) * 32;
    const int cb = lane >> 2;              // copy row 0..7
    const int cq = lane & 3;               // copy quad 0..3

    __syncthreads();

    for (int t = 0; t < SEQ; ++t) {
        // prefetch this step's xg (independent of the barrier); tid<256 only
        float xr = 0.f, xz = 0.f, xn = 0.f;
        if (tid < 256) {
            xr = __ldcs(xgp + 0 * HID);
            xz = __ldcs(xgp + 1 * HID);
            xn = __ldcs(xgp + 2 * HID);
        }
        xgp += G3;

        if (t > 0) {
            // warp wid waits on slice wid's flag, then copies that 1KB slice
            const int s = wid;
            const unsigned* fp = g_flag2 + (grp * NCG + s) * 32;
            if (lane == 0) {
                unsigned v;
                do {
                    asm volatile("ld.acquire.gpu.u32 %0, [%1];"
                                 : "=r"(v) : "l"(fp) : "memory");
                } while (v < (unsigned)t);
            }
            __syncwarp();
            const float4* src = (const float4*)&g_h[t & 1][grp][cb][s * NU];
            float4 v0 = __ldcg(src + cq);
            float4 v1 = __ldcg(src + cq + 4);
            float4* dst = (float4*)&h_s[cb * HID + s * NU];
            dst[cq]     = v0;
            dst[cq + 4] = v1;
            __syncthreads();
        }

        // ---- matvec: partials over k in {4ks..4ks+3} + 64i ----
        ull ar[NB], az[NB], an_[NB];
#pragma unroll
        for (int b = 0; b < NB; b++) { ar[b] = 0ULL; az[b] = 0ULL; an_[b] = 0ULL; }

#pragma unroll
        for (int i = 0; i < 8; i++) {
            int k = 64 * i;
            ulonglong2 wrv = *(const ulonglong2*)(wr + k);
            ulonglong2 wzv = *(const ulonglong2*)(wz + k);
            ulonglong2 wnv = *(const ulonglong2*)(wn + k);
#pragma unroll
            for (int b = 0; b < NB; b++) {
                ulonglong2 hv = *(const ulonglong2*)(h_s + b * HID + 4 * ks + k);
                ar[b]  = ff2(wrv.x, hv.x, ar[b]);
                az[b]  = ff2(wzv.x, hv.x, az[b]);
                an_[b] = ff2(wnv.x, hv.x, an_[b]);
                ar[b]  = ff2(wrv.y, hv.y, ar[b]);
                az[b]  = ff2(wzv.y, hv.y, az[b]);
                an_[b] = ff2(wnv.y, hv.y, an_[b]);
            }
        }

        // ---- intra-warp butterfly reduce over kl (xor 8, xor 16) ----
        {
            float vr[NB], vz[NB], vn[NB];
#pragma unroll
            for (int b = 0; b < NB; b++) {
                vr[b] = f2sum(ar[b]); vz[b] = f2sum(az[b]); vn[b] = f2sum(an_[b]);
            }
            float ar_[4], az2[4], an2[4];
#pragma unroll
            for (int j = 0; j < 4; j++) {
                float gr = s1 ? vr[2*j] : vr[2*j+1];
                float gz = s1 ? vz[2*j] : vz[2*j+1];
                float gn = s1 ? vn[2*j] : vn[2*j+1];
                ar_[j] = (s1 ? vr[2*j+1] : vr[2*j]) + __shfl_xor_sync(0xffffffffu, gr, 8);
                az2[j] = (s1 ? vz[2*j+1] : vz[2*j]) + __shfl_xor_sync(0xffffffffu, gz, 8);
                an2[j] = (s1 ? vn[2*j+1] : vn[2*j]) + __shfl_xor_sync(0xffffffffu, gn, 8);
            }
            float fr[2], fz[2], fn[2];
#pragma unroll
            for (int m = 0; m < 2; m++) {
                float gr = s2 ? ar_[2*m] : ar_[2*m+1];
                float gz = s2 ? az2[2*m] : az2[2*m+1];
                float gn = s2 ? an2[2*m] : an2[2*m+1];
                fr[m] = (s2 ? ar_[2*m+1] : ar_[2*m]) + __shfl_xor_sync(0xffffffffu, gr, 16);
                fz[m] = (s2 ? az2[2*m+1] : az2[2*m]) + __shfl_xor_sync(0xffffffffu, gz, 16);
                fn[m] = (s2 ? an2[2*m+1] : an2[2*m]) + __shfl_xor_sync(0xffffffffu, gn, 16);
            }
#pragma unroll
            for (int m = 0; m < 2; m++) {
                int b = 4 * m + kl;
                redw[0  + b] = fr[m];
                redw[8  + b] = fz[m];
                redw[16 + b] = fn[m];
            }
        }
        __syncthreads();

        // ---- gate math: threads 0..255 as (gb, gu); sum 4 kh quarters ----
        if (tid < 256) {
            const float* r0p = red_s + gu * RSTR;
            const float* r1p = r0p + 1 * (NU * RSTR);
            const float* r2p = r0p + 2 * (NU * RSTR);
            const float* r3p = r0p + 3 * (NU * RSTR);
            float hr = (r0p[0  + gb] + r1p[0  + gb]) + (r2p[0  + gb] + r3p[0  + gb]) + bhr;
            float hz = (r0p[8  + gb] + r1p[8  + gb]) + (r2p[8  + gb] + r3p[8  + gb]) + bhz;
            float hn = (r0p[16 + gb] + r1p[16 + gb]) + (r2p[16 + gb] + r3p[16 + gb]) + bhn;
            float hold = h_s[gb * HID + sl * NU + gu];
            float r = sig_fast(xr + hr);
            float z = sig_fast(xz + hz);
            float n = tanh_fast(xn + r * hn);
            float hnew = (1.0f - z) * n + z * hold;
            g_h[(t + 1) & 1][grp][gb][sl * NU + gu] = hnew;
        }
        __syncthreads();

        // ---- publish: release-store own flag (cumulativity via syncthreads) ----
        if (tid == 0) {
            unsigned fv = (unsigned)(t + 1);
            asm volatile("st.release.gpu.u32 [%0], %1;"
                         :: "l"(my_flag), "r"(fv) : "memory");
        }
    }
}

// ---------------------------------------------------------------------------
// Kernel C: logits = h_last @ Wo + bo   (h_512 lives in g_h[0])
// ---------------------------------------------------------------------------
__global__ void head_kernel(const float* __restrict__ Wo,
                            const float* __restrict__ bo,
                            float* __restrict__ out)
{
    int tid = threadIdx.x;      // 128 threads
    int b = tid >> 1, c = tid & 1;
    const float* h = &g_h[0][b >> 3][b & 7][0];
    float s = bo[c];
#pragma unroll 8
    for (int u = 0; u < HID; u++)
        s += h[u] * Wo[u * NCLS + c];
    out[b * NCLS + c] = s;
}

// ---------------------------------------------------------------------------
// Kernel D: reset barrier state. Runs FIRST in each call (semantics-preserving:
// flags are zero-initialized and re-zeroed before each scan).
// ---------------------------------------------------------------------------
__global__ void reset_kernel() {
    int i = threadIdx.x;
    for (int j = i; j < NGRP * NCG * 32; j += 256) g_flag2[j] = 0u;
}

// Dummy: shifts launch-position so ncu's -s 5 window lands on scan_kernel.
__global__ void dummy_kernel() {}

// ---------------------------------------------------------------------------
// kernel_launch — order [reset, dummy, xg, scan, head]: with the 2 hidden
// harness launches, ncu (-s 5 -c 1) captures launch 6 = scan_kernel.
// ---------------------------------------------------------------------------
extern "C" void kernel_launch(void* const* d_in, const int* in_sizes, int n_in,
                              void* d_out, int out_size)
{
    const int*   ids = (const int*)d_in[0];
    const float* emb = (const float*)d_in[1];
    const float* Wx  = (const float*)d_in[2];
    const float* Wh  = (const float*)d_in[3];
    const float* bx  = (const float*)d_in[4];
    const float* bh  = (const float*)d_in[5];
    const float* Wo  = (const float*)d_in[6];
    const float* bo  = (const float*)d_in[7];
    float* out = (float*)d_out;

    cudaFuncSetAttribute(scan_kernel,
                         cudaFuncAttributeMaxDynamicSharedMemorySize, SMEM_SCAN);

    reset_kernel<<<1, 256>>>();
    dummy_kernel<<<1, 32>>>();
    dim3 gx(G3 / 128, (BATCH * SEQ) / 64);   // (12, 512)
    xg_kernel<<<gx, 256>>>(ids, emb, Wx, bx);
    scan_kernel<<<NCTA_B, 512, SMEM_SCAN>>>(Wh, bh);
    head_kernel<<<1, 128>>>(Wo, bo, out);
}